// round 1
// baseline (speedup 1.0000x reference)
#include <cuda_runtime.h>
#include <math.h>

#define Dm   128
#define LVLS 7
#define Mn   32768
#define Nn   262144
#define Gg   5
#define TPB  512

// Per-level, per-gate node lists (built each replay; order nondeterministic but
// each node's computation is independent -> output bit-deterministic).
__device__ int g_counts[LVLS][Gg];
__device__ int g_lists[LVLS][Gg][Mn];

// ---------------------------------------------------------------------------
// zero hf level-0 slice (output region) + counts
// ---------------------------------------------------------------------------
__global__ void zero_kernel(float* __restrict__ hf) {
    int idx = blockIdx.x * blockDim.x + threadIdx.x;   // grid covers Mn*Dm/4 exactly
    ((float4*)hf)[idx] = make_float4(0.f, 0.f, 0.f, 0.f);
    if (blockIdx.x == 0 && threadIdx.x < LVLS * Gg)
        ((int*)g_counts)[threadIdx.x] = 0;
}

// ---------------------------------------------------------------------------
// bucket nodes by gate for all 7 levels
// ---------------------------------------------------------------------------
__global__ void bucket_kernel(const int* __restrict__ gate) {
    int idx = blockIdx.x * blockDim.x + threadIdx.x;
    if (idx >= LVLS * Mn) return;
    int li = idx / Mn;
    int m  = idx - li * Mn;
    int g  = gate[(li + 1) * Mn + m];
    int pos = atomicAdd(&g_counts[li][g], 1);
    g_lists[li][g][pos] = m;
}

// ---------------------------------------------------------------------------
// shared-memory GEMM micro-kernel:
//   acc[8][4] += A_T[k][r] * W[k][c]   (A_T in shared [K][128], W streamed via Wsh)
// thread (r0 = (tid&15)*8, c0 = (tid>>4)*4) owns an 8x4 output micro-tile.
// Caller guarantees a __syncthreads() before entry (Wsh free to overwrite).
// ---------------------------------------------------------------------------
__device__ __forceinline__ void gemm_accumulate(
    const float* __restrict__ A,    // shared, [K][128]
    const float* __restrict__ Wg,   // global, [K][128]
    float* __restrict__ Wsh,        // shared chunk buffer [32][128]
    int K, int tid, int r0, int c0, float acc[8][4])
{
    const int nchunks = K >> 5;
    for (int kc = 0; kc < nchunks; kc++) {
        const float4* wsrc = (const float4*)(Wg + (size_t)kc * 32 * 128);
        ((float4*)Wsh)[tid]       = wsrc[tid];
        ((float4*)Wsh)[tid + 512] = wsrc[tid + 512];
        __syncthreads();
        #pragma unroll 8
        for (int kk = 0; kk < 32; kk++) {
            const float* Ak = A + (kc * 32 + kk) * 128;
            float4 a0 = *(const float4*)(Ak + r0);
            float4 a1 = *(const float4*)(Ak + r0 + 4);
            float4 bv = *(const float4*)(Wsh + kk * 128 + c0);
            float a[8] = {a0.x, a0.y, a0.z, a0.w, a1.x, a1.y, a1.z, a1.w};
            float bb[4] = {bv.x, bv.y, bv.z, bv.w};
            #pragma unroll
            for (int i = 0; i < 8; i++)
                #pragma unroll
                for (int j = 0; j < 4; j++)
                    acc[i][j] = fmaf(a[i], bb[j], acc[i][j]);
        }
        __syncthreads();
    }
}

// ---------------------------------------------------------------------------
// hs = [s,t] @ hs_W + hs_b     (tile: 128 rows x 128 cols, K=256)
// ---------------------------------------------------------------------------
#define HS_SMEM ((256 * 128 + 32 * 128) * 4)

__global__ __launch_bounds__(TPB, 1)
void hs_kernel(const float* __restrict__ s, const float* __restrict__ t,
               const float* __restrict__ W, const float* __restrict__ b,
               float* __restrict__ out)
{
    extern __shared__ float sm[];
    float* Xt  = sm;              // [256][128] transposed input tile
    float* Wsh = sm + 256 * 128;  // [32][128]

    const int tid = threadIdx.x;
    const int n0  = blockIdx.x * 128;

    // gather: lane owns one row -> conflict-free transposed stores
    {
        const int r    = tid & 127;
        const int part = tid >> 7;
        const float* srow = s + (size_t)(n0 + r) * Dm;
        const float* trow = t + (size_t)(n0 + r) * Dm;
        #pragma unroll
        for (int j = 0; j < 16; j++) {
            int q = part + j * 4;   // float4 index 0..63 within the 256-wide row
            float4 v = (q < 32) ? ((const float4*)srow)[q]
                                : ((const float4*)trow)[q - 32];
            int k = q * 4;
            Xt[(k + 0) * 128 + r] = v.x;
            Xt[(k + 1) * 128 + r] = v.y;
            Xt[(k + 2) * 128 + r] = v.z;
            Xt[(k + 3) * 128 + r] = v.w;
        }
    }
    __syncthreads();

    const int ri = tid & 15, ci = tid >> 4;
    const int r0 = ri * 8,  c0 = ci * 4;

    float acc[8][4];
    #pragma unroll
    for (int i = 0; i < 8; i++)
        #pragma unroll
        for (int j = 0; j < 4; j++) acc[i][j] = 0.f;

    gemm_accumulate(Xt, W, Wsh, 256, tid, r0, c0, acc);

    float bb[4];
    #pragma unroll
    for (int j = 0; j < 4; j++) bb[j] = b[c0 + j];
    #pragma unroll
    for (int i = 0; i < 8; i++) {
        float4 o;
        o.x = acc[i][0] + bb[0];
        o.y = acc[i][1] + bb[1];
        o.z = acc[i][2] + bb[2];
        o.w = acc[i][3] + bb[3];
        *(float4*)&out[(size_t)(n0 + r0 + i) * Dm + c0] = o;
    }
}

// ---------------------------------------------------------------------------
// fused per-level kernel: gather -> MLP(3 GEMMs, per-gate) -> fanin-sum ->
// GRU input GEMM -> simplified GRU (h==0 => gh==bh) -> scatter to hf
// Tile: 64 nodes (128 gathered rows) of one gate.
// ---------------------------------------------------------------------------
#define LVL_SMEM_FLOATS (32768 + 16384 + 4096)
#define LVL_SMEM (LVL_SMEM_FLOATS * 4 + 64 * 4 + 128 * 4)

__global__ __launch_bounds__(TPB, 1)
void level_kernel(int li,
    const int*   __restrict__ fanin,
    const float* __restrict__ W1, const float* __restrict__ b1,
    const float* __restrict__ W2, const float* __restrict__ b2,
    const float* __restrict__ W3, const float* __restrict__ b3,
    const float* __restrict__ Wi, const float* __restrict__ bi,
    const float* __restrict__ bh,
    const float* __restrict__ hs, float* __restrict__ hf)
{
    extern __shared__ float sm[];
    float* buf0 = sm;                   // 32768 f: Xt[256][128] -> h2t[128][128] -> Wi chunk[16][384]
    float* buf1 = sm + 32768;           // 16384 f: h1t[128][128] -> msg_t[128][64]
    float* buf2 = sm + 32768 + 16384;   //  4096 f: W chunk [32][128]
    int* s_nodes = (int*)(sm + LVL_SMEM_FLOATS);  // 64
    int* s_src   = s_nodes + 64;                   // 128

    const int TILES = Mn / 64;  // 512
    const int g     = blockIdx.x / TILES;
    const int tile  = blockIdx.x - g * TILES;
    const int count = g_counts[li][g];
    const int base  = tile * 64;
    if (base >= count) return;
    const int valid = min(64, count - base);
    const int tid   = threadIdx.x;

    if (tid < 64) {
        int idx = base + tid;
        s_nodes[tid] = g_lists[li][g][idx < count ? idx : base];  // pad w/ dup (not written back)
    }
    __syncthreads();
    if (tid < 128) {
        int i = tid >> 1, f = tid & 1;
        int m = s_nodes[i];
        // global prev-level row = (lvl-1)*M + fanin[lvl-1][m][f] = li*M + ...
        s_src[tid] = li * Mn + fanin[((size_t)li * Mn + m) * 2 + f];
    }
    __syncthreads();

    // gather src_state = [hs[src], hf[src]] into transposed Xt
    {
        const int r    = tid & 127;
        const int part = tid >> 7;
        const int srow = s_src[r];
        const float* hsrow = hs + (size_t)srow * Dm;
        const float* hfrow = hf + (size_t)srow * Dm;
        #pragma unroll
        for (int j = 0; j < 16; j++) {
            int q = part + j * 4;
            float4 v = (q < 32) ? ((const float4*)hsrow)[q]
                                : ((const float4*)hfrow)[q - 32];
            int k = q * 4;
            buf0[(k + 0) * 128 + r] = v.x;
            buf0[(k + 1) * 128 + r] = v.y;
            buf0[(k + 2) * 128 + r] = v.z;
            buf0[(k + 3) * 128 + r] = v.w;
        }
    }
    __syncthreads();

    const int ri = tid & 15, ci = tid >> 4;
    const int r0 = ri * 8,  c0 = ci * 4;

    // ---- GEMM1: h1t(buf1) = relu(Xt @ W1[g] + b1[g]), K=256 ----
    {
        float acc[8][4];
        #pragma unroll
        for (int i = 0; i < 8; i++)
            #pragma unroll
            for (int j = 0; j < 4; j++) acc[i][j] = 0.f;
        gemm_accumulate(buf0, W1 + (size_t)g * 256 * 128, buf2, 256, tid, r0, c0, acc);
        float bb[4];
        #pragma unroll
        for (int j = 0; j < 4; j++) bb[j] = b1[g * Dm + c0 + j];
        #pragma unroll
        for (int i = 0; i < 8; i++)
            #pragma unroll
            for (int j = 0; j < 4; j++)
                buf1[(c0 + j) * 128 + (r0 + i)] = fmaxf(acc[i][j] + bb[j], 0.f);
    }
    __syncthreads();

    // ---- GEMM2: h2t(buf0) = relu(h1t @ W2[g] + b2[g]), K=128 ----
    {
        float acc[8][4];
        #pragma unroll
        for (int i = 0; i < 8; i++)
            #pragma unroll
            for (int j = 0; j < 4; j++) acc[i][j] = 0.f;
        gemm_accumulate(buf1, W2 + (size_t)g * 128 * 128, buf2, 128, tid, r0, c0, acc);
        float bb[4];
        #pragma unroll
        for (int j = 0; j < 4; j++) bb[j] = b2[g * Dm + c0 + j];
        #pragma unroll
        for (int i = 0; i < 8; i++)
            #pragma unroll
            for (int j = 0; j < 4; j++)
                buf0[(c0 + j) * 128 + (r0 + i)] = fmaxf(acc[i][j] + bb[j], 0.f);
    }
    __syncthreads();

    // ---- GEMM3: msg_t(buf1) = sum_f(h2t @ W3[g]) + 2*b3[g], K=128 ----
    // rows (2n, 2n+1) are the f=0/1 rows of node n; this thread owns 4 node pairs.
    {
        float acc[8][4];
        #pragma unroll
        for (int i = 0; i < 8; i++)
            #pragma unroll
            for (int j = 0; j < 4; j++) acc[i][j] = 0.f;
        gemm_accumulate(buf0, W3 + (size_t)g * 128 * 128, buf2, 128, tid, r0, c0, acc);
        float bb[4];
        #pragma unroll
        for (int j = 0; j < 4; j++) bb[j] = 2.f * b3[g * Dm + c0 + j];
        #pragma unroll
        for (int p = 0; p < 4; p++)
            #pragma unroll
            for (int j = 0; j < 4; j++)
                buf1[(c0 + j) * 64 + (ri * 4 + p)] =
                    acc[2 * p][j] + acc[2 * p + 1][j] + bb[j];
    }
    __syncthreads();

    // ---- GEMM4 + GRU: gi = msg @ Wi[g] + bi[g]; gh == bh[g] (h == 0) ----
    {
        const float* Wg = Wi + (size_t)g * 128 * 384;
        const int d  = tid & 127;
        const int nl = tid >> 7;   // node residue 0..3; node = nl + 4*j
        float aR[16], aZ[16], aN[16];
        #pragma unroll
        for (int j = 0; j < 16; j++) { aR[j] = 0.f; aZ[j] = 0.f; aN[j] = 0.f; }

        for (int kc = 0; kc < 8; kc++) {
            const float4* wsrc = (const float4*)(Wg + (size_t)kc * 16 * 384);
            ((float4*)buf0)[tid]        = wsrc[tid];
            ((float4*)buf0)[tid + 512]  = wsrc[tid + 512];
            ((float4*)buf0)[tid + 1024] = wsrc[tid + 1024];
            __syncthreads();
            #pragma unroll 4
            for (int kk = 0; kk < 16; kk++) {
                int k = kc * 16 + kk;
                float wr = buf0[kk * 384 + d];
                float wz = buf0[kk * 384 + 128 + d];
                float wn = buf0[kk * 384 + 256 + d];
                #pragma unroll
                for (int j = 0; j < 16; j++) {
                    float mv = buf1[k * 64 + nl + j * 4];
                    aR[j] = fmaf(mv, wr, aR[j]);
                    aZ[j] = fmaf(mv, wz, aZ[j]);
                    aN[j] = fmaf(mv, wn, aN[j]);
                }
            }
            __syncthreads();
        }

        const float bir = bi[g * 384 + d],       bhr = bh[g * 384 + d];
        const float biz = bi[g * 384 + 128 + d], bhz = bh[g * 384 + 128 + d];
        const float bin = bi[g * 384 + 256 + d], bhn = bh[g * 384 + 256 + d];
        #pragma unroll
        for (int j = 0; j < 16; j++) {
            int n = nl + j * 4;
            if (n < valid) {
                float rg = 1.f / (1.f + expf(-(aR[j] + bir + bhr)));
                float zg = 1.f / (1.f + expf(-(aZ[j] + biz + bhz)));
                float ng = tanhf(aN[j] + bin + rg * bhn);
                int m = s_nodes[n];
                hf[((size_t)(li + 1) * Mn + m) * Dm + d] = (1.f - zg) * ng;
            }
        }
    }
}

// ---------------------------------------------------------------------------
extern "C" void kernel_launch(void* const* d_in, const int* in_sizes, int n_in,
                              void* d_out, int out_size)
{
    const float* s    = (const float*)d_in[0];
    const float* t    = (const float*)d_in[1];
    const int*   gate = (const int*)  d_in[2];
    const int*   fan  = (const int*)  d_in[3];
    const float* hsW  = (const float*)d_in[4];
    const float* hsb  = (const float*)d_in[5];
    const float* W1   = (const float*)d_in[6];
    const float* b1   = (const float*)d_in[7];
    const float* W2   = (const float*)d_in[8];
    const float* b2   = (const float*)d_in[9];
    const float* W3   = (const float*)d_in[10];
    const float* b3   = (const float*)d_in[11];
    const float* Wi   = (const float*)d_in[12];
    // d_in[13] = gru_Wh: provably unused (h == 0 at every level)
    const float* bi   = (const float*)d_in[14];
    const float* bh   = (const float*)d_in[15];

    float* hs = (float*)d_out;                 // output part 0: hs [N, D]
    float* hf = hs + (size_t)Nn * Dm;          // output part 1: hf [N, D]

    cudaFuncSetAttribute(hs_kernel,    cudaFuncAttributeMaxDynamicSharedMemorySize, HS_SMEM);
    cudaFuncSetAttribute(level_kernel, cudaFuncAttributeMaxDynamicSharedMemorySize, LVL_SMEM);

    zero_kernel<<<(Mn * Dm / 4) / TPB, TPB>>>(hf);
    bucket_kernel<<<(LVLS * Mn + TPB - 1) / TPB, TPB>>>(gate);
    hs_kernel<<<Nn / 128, TPB, HS_SMEM>>>(s, t, hsW, hsb, hs);
    for (int li = 0; li < LVLS; li++) {
        level_kernel<<<Gg * (Mn / 64), TPB, LVL_SMEM>>>(
            li, fan, W1, b1, W2, b2, W3, b3, Wi, bi, bh, hs, hf);
    }
}

// round 12
// speedup vs baseline: 2.4729x; 2.4729x over previous
#include <cuda_runtime.h>
#include <math.h>
#include <stdint.h>

#define Dm   128
#define LVLS 7
#define Mn   32768
#define Nn   262144
#define Gg   5
#define TPB  512

// ---- shared memory layout (float indices) ----
#define PAD     136                       // k-major buffers [K][PAD]; 136%32=8 -> conflict-free frags
#define A_OFF   0                         // A / intermediate buffer: 256*136 = 34816 floats
#define W_OFF   34816                     // weight chunk buffer: up to 16*392 = 6272 floats
#define MSG_OFF 41088                     // msg [128][72] = 9216 floats
#define TOT_F   50304
#define NODES_B (TOT_F * 4)               // 64 ints
#define SRC_B   (NODES_B + 256)           // 128 ints
#define SMEM_TOTAL (SRC_B + 512)

__device__ int g_counts[LVLS][Gg];
__device__ int g_lists[LVLS][Gg][Mn];

// ---------------------------------------------------------------------------
// helpers
// ---------------------------------------------------------------------------
__device__ __forceinline__ float to_tf32(float x) {
    float y;
    asm("cvt.rna.tf32.f32 %0, %1;" : "=f"(y) : "f"(x));
    return y;
}

// D(16x8) += A(16x8) * B(8x8), tf32 inputs, f32 accum.
__device__ __forceinline__ void mma8(float* d, const float* a, const float* b) {
    asm volatile(
        "mma.sync.aligned.m16n8k8.row.col.f32.tf32.tf32.f32 "
        "{%0,%1,%2,%3}, {%4,%5,%6,%7}, {%8,%9}, {%0,%1,%2,%3};"
        : "+f"(d[0]), "+f"(d[1]), "+f"(d[2]), "+f"(d[3])
        : "r"(__float_as_uint(a[0])), "r"(__float_as_uint(a[1])),
          "r"(__float_as_uint(a[2])), "r"(__float_as_uint(a[3])),
          "r"(__float_as_uint(b[0])), "r"(__float_as_uint(b[1])));
}

// ---------------------------------------------------------------------------
// setup kernels
// ---------------------------------------------------------------------------
__global__ void zero_kernel(float* __restrict__ hf) {
    int idx = blockIdx.x * blockDim.x + threadIdx.x;
    ((float4*)hf)[idx] = make_float4(0.f, 0.f, 0.f, 0.f);
    if (blockIdx.x == 0 && threadIdx.x < LVLS * Gg)
        ((int*)g_counts)[threadIdx.x] = 0;
}

__global__ void bucket_kernel(const int* __restrict__ gate) {
    int idx = blockIdx.x * blockDim.x + threadIdx.x;
    if (idx >= LVLS * Mn) return;
    int li = idx / Mn, m = idx - li * Mn;
    int g = gate[(li + 1) * Mn + m];
    int pos = atomicAdd(&g_counts[li][g], 1);
    g_lists[li][g][pos] = m;
}

// ---------------------------------------------------------------------------
// 128x128 GEMM: D = A(smem, k-major [K][PAD]) @ W(global, k-major [K][128])
// 16 warps as 4x4 grid, each 32 rows x 32 cols. acc[2 rowtiles][4 coltiles][4].
// Weight chunks of 32 K-rows staged in Wsh [32][PAD], with register prefetch
// of the NEXT chunk issued before the MMA phase (hides L2 latency).
// ---------------------------------------------------------------------------
__device__ void gemm128(float* sm, const float* __restrict__ Wg, int K,
                        int tid, float acc[2][4][4]) {
    const float* As = sm + A_OFF;
    float* Wsh = sm + W_OFF;
    int warp = tid >> 5, lane = tid & 31;
    int lr = lane >> 2, lk = lane & 3;
    int rowb = (warp >> 2) * 32, colb = (warp & 3) * 32;
    const int k0i = tid >> 5, nq = tid & 31;      // this thread's chunk-row / quad
    const int k1i = (tid + 512) >> 5;

    // prologue prefetch: chunk 0
    float4 pre0 = ((const float4*)(Wg + (size_t)k0i * 128))[nq];
    float4 pre1 = ((const float4*)(Wg + (size_t)k1i * 128))[nq];

    for (int kc = 0; kc < K; kc += 32) {
        // store staged chunk (tf32-rounded at store time)
        float4 v0 = pre0, v1 = pre1;
        v0.x = to_tf32(v0.x); v0.y = to_tf32(v0.y); v0.z = to_tf32(v0.z); v0.w = to_tf32(v0.w);
        v1.x = to_tf32(v1.x); v1.y = to_tf32(v1.y); v1.z = to_tf32(v1.z); v1.w = to_tf32(v1.w);
        *(float4*)(Wsh + k0i * PAD + nq * 4) = v0;
        *(float4*)(Wsh + k1i * PAD + nq * 4) = v1;
        __syncthreads();

        // prefetch NEXT chunk while MMA phase runs
        if (kc + 32 < K) {
            pre0 = ((const float4*)(Wg + (size_t)(kc + 32 + k0i) * 128))[nq];
            pre1 = ((const float4*)(Wg + (size_t)(kc + 32 + k1i) * 128))[nq];
        }

        #pragma unroll
        for (int s = 0; s < 4; s++) {
            int k0 = s * 8;
            float a[2][4];
            #pragma unroll
            for (int rt = 0; rt < 2; rt++) {
                int row = rowb + rt * 16 + lr;
                a[rt][0] = As[(size_t)(kc + k0 + lk) * PAD + row];
                a[rt][1] = As[(size_t)(kc + k0 + lk) * PAD + row + 8];
                a[rt][2] = As[(size_t)(kc + k0 + 4 + lk) * PAD + row];
                a[rt][3] = As[(size_t)(kc + k0 + 4 + lk) * PAD + row + 8];
            }
            #pragma unroll
            for (int ct = 0; ct < 4; ct++) {
                int col = colb + ct * 8 + lr;
                float b[2];
                b[0] = Wsh[(k0 + lk) * PAD + col];
                b[1] = Wsh[(k0 + 4 + lk) * PAD + col];
                mma8(acc[0][ct], a[0], b);
                mma8(acc[1][ct], a[1], b);
            }
        }
        __syncthreads();
    }
}

// relu(x+bias) epilogue -> k-major intermediate at A_OFF ([col][PAD] layout)
__device__ void epi_relu(float* sm, const float* __restrict__ bias,
                         int tid, float acc[2][4][4]) {
    float* B = sm + A_OFF;
    int warp = tid >> 5, lane = tid & 31;
    int lr = lane >> 2, lk = lane & 3;
    int rowb = (warp >> 2) * 32, colb = (warp & 3) * 32;
    #pragma unroll
    for (int rt = 0; rt < 2; rt++)
        #pragma unroll
        for (int ct = 0; ct < 4; ct++) {
            int row = rowb + rt * 16 + lr, col = colb + ct * 8 + 2 * lk;
            float b0 = bias[col], b1 = bias[col + 1];
            B[(col)     * PAD + row]     = to_tf32(fmaxf(acc[rt][ct][0] + b0, 0.f));
            B[(col + 1) * PAD + row]     = to_tf32(fmaxf(acc[rt][ct][1] + b1, 0.f));
            B[(col)     * PAD + row + 8] = to_tf32(fmaxf(acc[rt][ct][2] + b0, 0.f));
            B[(col + 1) * PAD + row + 8] = to_tf32(fmaxf(acc[rt][ct][3] + b1, 0.f));
        }
}

// raw epilogue (no bias) -> k-major intermediate at A_OFF
__device__ void epi_raw(float* sm, int tid, float acc[2][4][4]) {
    float* B = sm + A_OFF;
    int warp = tid >> 5, lane = tid & 31;
    int lr = lane >> 2, lk = lane & 3;
    int rowb = (warp >> 2) * 32, colb = (warp & 3) * 32;
    #pragma unroll
    for (int rt = 0; rt < 2; rt++)
        #pragma unroll
        for (int ct = 0; ct < 4; ct++) {
            int row = rowb + rt * 16 + lr, col = colb + ct * 8 + 2 * lk;
            B[(col)     * PAD + row]     = acc[rt][ct][0];
            B[(col + 1) * PAD + row]     = acc[rt][ct][1];
            B[(col)     * PAD + row + 8] = acc[rt][ct][2];
            B[(col + 1) * PAD + row + 8] = acc[rt][ct][3];
        }
}

// ---------------------------------------------------------------------------
// hs = [s,t] @ hs_W + hs_b
// ---------------------------------------------------------------------------
__global__ __launch_bounds__(TPB, 1)
void hs_kernel(const float* __restrict__ s, const float* __restrict__ t,
               const float* __restrict__ hsW, const float* __restrict__ hsb,
               float* __restrict__ out)
{
    extern __shared__ float sm[];
    int tid = threadIdx.x;
    int n0 = blockIdx.x * 128;

    // gather [s||t] rows into k-major A [256][PAD], tf32-rounded
    {
        int r = tid & 127, part = tid >> 7;
        const float* p0 = s + (size_t)(n0 + r) * Dm;
        const float* p1 = t + (size_t)(n0 + r) * Dm;
        #pragma unroll
        for (int j = 0; j < 16; j++) {
            int q = part + 4 * j;
            float4 v = (q < 32) ? ((const float4*)p0)[q] : ((const float4*)p1)[q - 32];
            int k = q * 4;
            sm[A_OFF + (size_t)(k + 0) * PAD + r] = to_tf32(v.x);
            sm[A_OFF + (size_t)(k + 1) * PAD + r] = to_tf32(v.y);
            sm[A_OFF + (size_t)(k + 2) * PAD + r] = to_tf32(v.z);
            sm[A_OFF + (size_t)(k + 3) * PAD + r] = to_tf32(v.w);
        }
    }
    __syncthreads();

    float acc[2][4][4];
    #pragma unroll
    for (int i = 0; i < 2; i++)
        #pragma unroll
        for (int j = 0; j < 4; j++)
            #pragma unroll
            for (int q = 0; q < 4; q++) acc[i][j][q] = 0.f;

    gemm128(sm, hsW, 256, tid, acc);

    // bias + store to global
    {
        int warp = tid >> 5, lane = tid & 31;
        int lr = lane >> 2, lk = lane & 3;
        int rowb = (warp >> 2) * 32, colb = (warp & 3) * 32;
        #pragma unroll
        for (int rt = 0; rt < 2; rt++)
            #pragma unroll
            for (int ct = 0; ct < 4; ct++) {
                int row = rowb + rt * 16 + lr, col = colb + ct * 8 + 2 * lk;
                float b0 = hsb[col], b1 = hsb[col + 1];
                float2 v0 = make_float2(acc[rt][ct][0] + b0, acc[rt][ct][1] + b1);
                float2 v1 = make_float2(acc[rt][ct][2] + b0, acc[rt][ct][3] + b1);
                *(float2*)(out + (size_t)(n0 + row) * Dm + col)     = v0;
                *(float2*)(out + (size_t)(n0 + row + 8) * Dm + col) = v1;
            }
    }
}

// ---------------------------------------------------------------------------
// per-level fused kernel: 64 nodes (128 gathered rows) per block
// ---------------------------------------------------------------------------
__global__ __launch_bounds__(TPB, 1)
void level_kernel(int li, const int* __restrict__ fanin,
                  const float* __restrict__ W1, const float* __restrict__ b1,
                  const float* __restrict__ W2, const float* __restrict__ b2,
                  const float* __restrict__ W3, const float* __restrict__ b3,
                  const float* __restrict__ Wi, const float* __restrict__ bi,
                  const float* __restrict__ bh,
                  const float* __restrict__ hs, float* __restrict__ hf)
{
    extern __shared__ float sm[];
    const int TILES = Mn / 64;  // 512
    int g = blockIdx.x / TILES, tile = blockIdx.x - g * TILES;
    int count = g_counts[li][g];
    int base = tile * 64;
    if (base >= count) return;
    int valid = min(64, count - base);
    int tid = threadIdx.x;

    int* s_nodes = (int*)((char*)sm + NODES_B);
    int* s_src   = (int*)((char*)sm + SRC_B);

    if (tid < 64) {
        int i = base + tid;
        s_nodes[tid] = g_lists[li][g][i < count ? i : base];
    }
    __syncthreads();
    if (tid < 128) {
        int i = tid >> 1, f = tid & 1;
        int m = s_nodes[i];
        s_src[tid] = li * Mn + fanin[((size_t)li * Mn + m) * 2 + f];
    }
    __syncthreads();

    // gather [hs||hf] of 128 source rows into A [256][PAD]
    {
        int r = tid & 127, part = tid >> 7;
        int srow = s_src[r];
        const float* p0 = hs + (size_t)srow * Dm;
        const float* p1 = hf + (size_t)srow * Dm;
        #pragma unroll
        for (int j = 0; j < 16; j++) {
            int q = part + 4 * j;
            float4 v = (q < 32) ? ((const float4*)p0)[q] : ((const float4*)p1)[q - 32];
            int k = q * 4;
            sm[A_OFF + (size_t)(k + 0) * PAD + r] = to_tf32(v.x);
            sm[A_OFF + (size_t)(k + 1) * PAD + r] = to_tf32(v.y);
            sm[A_OFF + (size_t)(k + 2) * PAD + r] = to_tf32(v.z);
            sm[A_OFF + (size_t)(k + 3) * PAD + r] = to_tf32(v.w);
        }
    }
    __syncthreads();

    float acc[2][4][4];
    #define ZACC() { _Pragma("unroll") for (int i = 0; i < 2; i++) \
                     _Pragma("unroll") for (int j = 0; j < 4; j++) \
                     _Pragma("unroll") for (int q = 0; q < 4; q++) acc[i][j][q] = 0.f; }

    // GEMM1: h1 = relu(X @ W1 + b1), K=256
    ZACC();
    gemm128(sm, W1 + (size_t)g * 256 * 128, 256, tid, acc);
    epi_relu(sm, b1 + g * Dm, tid, acc);
    __syncthreads();

    // GEMM2: h2 = relu(h1 @ W2 + b2), K=128
    ZACC();
    gemm128(sm, W2 + (size_t)g * 128 * 128, 128, tid, acc);
    epi_relu(sm, b2 + g * Dm, tid, acc);
    __syncthreads();

    // GEMM3: m = h2 @ W3 (raw), K=128
    ZACC();
    gemm128(sm, W3 + (size_t)g * 128 * 128, 128, tid, acc);
    epi_raw(sm, tid, acc);
    __syncthreads();

    // pair-sum fanin rows + 2*b3 -> msg [128 col][72] (tf32)
    {
        const float* mbuf = sm + A_OFF;
        float* msg = sm + MSG_OFF;
        #pragma unroll
        for (int j = 0; j < 16; j++) {
            int idx = tid + j * 512;            // 8192 = 128 cols x 64 nodes
            int col = idx >> 6, node = idx & 63;
            float v = mbuf[col * PAD + 2 * node] + mbuf[col * PAD + 2 * node + 1]
                    + 2.f * b3[g * Dm + col];
            msg[col * 72 + node] = to_tf32(v);
        }
    }
    __syncthreads();

    // GEMM4: gi = msg @ Wi, M=64, N=384, K=128.
    // 16 warps: 4 row groups (16 nodes) x 4 col groups (96 cols = 12 mma tiles).
    // W chunk [16][384] staged in Wsh [16][392] with register prefetch.
    {
        const float* msg = sm + MSG_OFF;
        float* Wsh = sm + W_OFF;                // [16][392]
        float* gibuf = sm + A_OFF;              // [384 col][65 node]
        int warp = tid >> 5, lane = tid & 31;
        int lr = lane >> 2, lk = lane & 3;
        int rowb = (warp & 3) * 16, colb = (warp >> 2) * 96;
        const float* Wg = Wi + (size_t)g * 128 * 384;

        // per-thread staging coords for the 3 float4s
        int kk[3], qq[3];
        #pragma unroll
        for (int j = 0; j < 3; j++) {
            int idx = tid + j * 512;            // 1536 float4 = 16 x 96
            kk[j] = idx / 96; qq[j] = idx - kk[j] * 96;
        }

        float acc4[12][4];
        #pragma unroll
        for (int i = 0; i < 12; i++)
            #pragma unroll
            for (int q = 0; q < 4; q++) acc4[i][q] = 0.f;

        // prologue prefetch: chunk 0
        float4 pre[3];
        #pragma unroll
        for (int j = 0; j < 3; j++)
            pre[j] = ((const float4*)(Wg + (size_t)kk[j] * 384))[qq[j]];

        for (int kc = 0; kc < 128; kc += 16) {
            #pragma unroll
            for (int j = 0; j < 3; j++) {
                float4 v = pre[j];
                v.x = to_tf32(v.x); v.y = to_tf32(v.y);
                v.z = to_tf32(v.z); v.w = to_tf32(v.w);
                *(float4*)(Wsh + kk[j] * 392 + qq[j] * 4) = v;
            }
            __syncthreads();

            // prefetch next chunk during MMA phase
            if (kc + 16 < 128) {
                #pragma unroll
                for (int j = 0; j < 3; j++)
                    pre[j] = ((const float4*)(Wg + (size_t)(kc + 16 + kk[j]) * 384))[qq[j]];
            }

            #pragma unroll
            for (int s2 = 0; s2 < 2; s2++) {
                int k0 = s2 * 8;
                float a[4];
                int row = rowb + lr;
                a[0] = msg[(size_t)(kc + k0 + lk) * 72 + row];
                a[1] = msg[(size_t)(kc + k0 + lk) * 72 + row + 8];
                a[2] = msg[(size_t)(kc + k0 + 4 + lk) * 72 + row];
                a[3] = msg[(size_t)(kc + k0 + 4 + lk) * 72 + row + 8];
                #pragma unroll
                for (int ct = 0; ct < 12; ct++) {
                    int col = colb + ct * 8 + lr;
                    float b[2];
                    b[0] = Wsh[(k0 + lk) * 392 + col];
                    b[1] = Wsh[(k0 + 4 + lk) * 392 + col];
                    mma8(acc4[ct], a, b);
                }
            }
            __syncthreads();
        }

        // epilogue -> gibuf[col][node] (col-major, node stride 65)
        #pragma unroll
        for (int ct = 0; ct < 12; ct++) {
            int col = colb + ct * 8 + 2 * lk;
            int node = rowb + lr;
            gibuf[(col)     * 65 + node]     = acc4[ct][0];
            gibuf[(col + 1) * 65 + node]     = acc4[ct][1];
            gibuf[(col)     * 65 + node + 8] = acc4[ct][2];
            gibuf[(col + 1) * 65 + node + 8] = acc4[ct][3];
        }
    }
    __syncthreads();

    // GRU epilogue (h == 0 -> gh == bh): coalesced hf writes (lanes = d)
    {
        const float* gibuf = sm + A_OFF;
        int d = tid & 127, nq = tid >> 7;
        float bir = bi[g * 384 + d],       bhr = bh[g * 384 + d];
        float biz = bi[g * 384 + 128 + d], bhz = bh[g * 384 + 128 + d];
        float bin = bi[g * 384 + 256 + d], bhn = bh[g * 384 + 256 + d];
        #pragma unroll
        for (int j = 0; j < 16; j++) {
            int node = nq * 16 + j;
            float gr = gibuf[(d)       * 65 + node] + bir + bhr;
            float gz = gibuf[(128 + d) * 65 + node] + biz + bhz;
            float gn = gibuf[(256 + d) * 65 + node] + bin;
            float rg = 1.f / (1.f + expf(-gr));
            float zg = 1.f / (1.f + expf(-gz));
            float ng = tanhf(gn + rg * bhn);
            if (node < valid) {
                int m = s_nodes[node];
                hf[((size_t)(li + 1) * Mn + m) * Dm + d] = (1.f - zg) * ng;
            }
        }
    }
}

// ---------------------------------------------------------------------------
extern "C" void kernel_launch(void* const* d_in, const int* in_sizes, int n_in,
                              void* d_out, int out_size)
{
    const float* s    = (const float*)d_in[0];
    const float* t    = (const float*)d_in[1];
    const int*   gate = (const int*)  d_in[2];
    const int*   fan  = (const int*)  d_in[3];
    const float* hsW  = (const float*)d_in[4];
    const float* hsb  = (const float*)d_in[5];
    const float* W1   = (const float*)d_in[6];
    const float* b1   = (const float*)d_in[7];
    const float* W2   = (const float*)d_in[8];
    const float* b2   = (const float*)d_in[9];
    const float* W3   = (const float*)d_in[10];
    const float* b3   = (const float*)d_in[11];
    const float* Wi   = (const float*)d_in[12];
    // d_in[13] = gru_Wh: provably unused (h == 0 at every level)
    const float* bi   = (const float*)d_in[14];
    const float* bh   = (const float*)d_in[15];

    float* hs = (float*)d_out;
    float* hf = hs + (size_t)Nn * Dm;

    cudaFuncSetAttribute(hs_kernel,    cudaFuncAttributeMaxDynamicSharedMemorySize, SMEM_TOTAL);
    cudaFuncSetAttribute(level_kernel, cudaFuncAttributeMaxDynamicSharedMemorySize, SMEM_TOTAL);

    zero_kernel<<<(Mn * Dm / 4) / TPB, TPB>>>(hf);
    bucket_kernel<<<(LVLS * Mn + TPB - 1) / TPB, TPB>>>(gate);
    hs_kernel<<<Nn / 128, TPB, SMEM_TOTAL>>>(s, t, hsW, hsb, hs);
    for (int li = 0; li < LVLS; li++) {
        level_kernel<<<Gg * (Mn / 64), TPB, SMEM_TOTAL>>>(
            li, fan, W1, b1, W2, b2, W3, b3, Wi, bi, bh, hs, hf);
    }
}

// round 17
// speedup vs baseline: 2.7044x; 1.0936x over previous
#include <cuda_runtime.h>
#include <math.h>
#include <stdint.h>

#define Dm   128
#define LVLS 7
#define Mn   32768
#define Nn   262144
#define Gg   5
#define TPB  512

// ---- shared memory layout (float indices) ----
#define PAD     136                   // A buffer [K][PAD]; 136%32=8 -> conflict-free frags
#define A_OFF   0                     // 256*136 = 34816 floats
#define W_OFF   34816                 // 12544 floats: 2 ping-pong W buffers (gemm128: 2x4352, gemm4: 2x6272)
#define MSG_OFF 47360                 // msg [128][72] = 9216 floats
#define TOT_F   56576
#define NODES_B (TOT_F * 4)           // 64 ints
#define SRC_B   (NODES_B + 256)       // 128 ints
#define SMEM_TOTAL (SRC_B + 512)      // 227072 B <= 227KB opt-in

__device__ int g_counts[LVLS][Gg];
__device__ int g_lists[LVLS][Gg][Mn];

// ---------------------------------------------------------------------------
// helpers
// ---------------------------------------------------------------------------
__device__ __forceinline__ float to_tf32(float x) {
    float y;
    asm("cvt.rna.tf32.f32 %0, %1;" : "=f"(y) : "f"(x));
    return y;
}
__device__ __forceinline__ float4 tf32x4(float4 v) {
    v.x = to_tf32(v.x); v.y = to_tf32(v.y);
    v.z = to_tf32(v.z); v.w = to_tf32(v.w);
    return v;
}

// D(16x8) += A(16x8) * B(8x8), tf32 inputs, f32 accum.
__device__ __forceinline__ void mma8(float* d, const float* a, const float* b) {
    asm volatile(
        "mma.sync.aligned.m16n8k8.row.col.f32.tf32.tf32.f32 "
        "{%0,%1,%2,%3}, {%4,%5,%6,%7}, {%8,%9}, {%0,%1,%2,%3};"
        : "+f"(d[0]), "+f"(d[1]), "+f"(d[2]), "+f"(d[3])
        : "r"(__float_as_uint(a[0])), "r"(__float_as_uint(a[1])),
          "r"(__float_as_uint(a[2])), "r"(__float_as_uint(a[3])),
          "r"(__float_as_uint(b[0])), "r"(__float_as_uint(b[1])));
}

// ---------------------------------------------------------------------------
// setup kernels
// ---------------------------------------------------------------------------
__global__ void zero_kernel(float* __restrict__ hf) {
    int idx = blockIdx.x * blockDim.x + threadIdx.x;
    ((float4*)hf)[idx] = make_float4(0.f, 0.f, 0.f, 0.f);
    if (blockIdx.x == 0 && threadIdx.x < LVLS * Gg)
        ((int*)g_counts)[threadIdx.x] = 0;
}

__global__ void bucket_kernel(const int* __restrict__ gate) {
    int idx = blockIdx.x * blockDim.x + threadIdx.x;
    if (idx >= LVLS * Mn) return;
    int li = idx / Mn, m = idx - li * Mn;
    int g = gate[(li + 1) * Mn + m];
    int pos = atomicAdd(&g_counts[li][g], 1);
    g_lists[li][g][pos] = m;
}

// ---------------------------------------------------------------------------
// 128x128 GEMM: D = A(smem, k-major [K][PAD]) @ W(global, k-major [K][128])
// 16 warps as 4x4 grid, each 32x32. Double-buffered W staging (ping-pong):
// ONE barrier per 32-K chunk; next chunk LDG-prefetched during MMA phase.
// ---------------------------------------------------------------------------
__device__ void gemm128(float* sm, const float* __restrict__ Wg, int K,
                        int tid, float acc[2][4][4]) {
    const float* As = sm + A_OFF;
    float* Wsh = sm + W_OFF;                 // 2 x 4352 floats ([32][136])
    int warp = tid >> 5, lane = tid & 31;
    int lr = lane >> 2, lk = lane & 3;
    int rowb = (warp >> 2) * 32, colb = (warp & 3) * 32;
    const int k0i = tid >> 5, nq = tid & 31; // staging coords
    const int k1i = k0i + 16;
    const int nchunk = K >> 5;

    // prologue: stage chunk 0, prefetch chunk 1
    float4 pre0 = ((const float4*)(Wg + (size_t)k0i * 128))[nq];
    float4 pre1 = ((const float4*)(Wg + (size_t)k1i * 128))[nq];
    *(float4*)(Wsh + k0i * PAD + nq * 4) = tf32x4(pre0);
    *(float4*)(Wsh + k1i * PAD + nq * 4) = tf32x4(pre1);
    if (nchunk > 1) {
        pre0 = ((const float4*)(Wg + (size_t)(32 + k0i) * 128))[nq];
        pre1 = ((const float4*)(Wg + (size_t)(32 + k1i) * 128))[nq];
    }
    __syncthreads();

    for (int c = 0; c < nchunk; c++) {
        const float* Wb = Wsh + (c & 1) * 4352;
        int kc = c * 32;
        #pragma unroll
        for (int s = 0; s < 4; s++) {
            int k0 = s * 8;
            float a[2][4];
            #pragma unroll
            for (int rt = 0; rt < 2; rt++) {
                int row = rowb + rt * 16 + lr;
                a[rt][0] = As[(size_t)(kc + k0 + lk) * PAD + row];
                a[rt][1] = As[(size_t)(kc + k0 + lk) * PAD + row + 8];
                a[rt][2] = As[(size_t)(kc + k0 + 4 + lk) * PAD + row];
                a[rt][3] = As[(size_t)(kc + k0 + 4 + lk) * PAD + row + 8];
            }
            #pragma unroll
            for (int ct = 0; ct < 4; ct++) {
                int col = colb + ct * 8 + lr;
                float b[2];
                b[0] = Wb[(k0 + lk) * PAD + col];
                b[1] = Wb[(k0 + 4 + lk) * PAD + col];
                mma8(acc[0][ct], a[0], b);
                mma8(acc[1][ct], a[1], b);
            }
        }
        // stage next chunk into opposite buffer; prefetch chunk c+2
        if (c + 1 < nchunk) {
            float* Wn = Wsh + ((c + 1) & 1) * 4352;
            *(float4*)(Wn + k0i * PAD + nq * 4) = tf32x4(pre0);
            *(float4*)(Wn + k1i * PAD + nq * 4) = tf32x4(pre1);
            if (c + 2 < nchunk) {
                pre0 = ((const float4*)(Wg + (size_t)((c + 2) * 32 + k0i) * 128))[nq];
                pre1 = ((const float4*)(Wg + (size_t)((c + 2) * 32 + k1i) * 128))[nq];
            }
        }
        __syncthreads();
    }
}

// relu(x+bias) epilogue -> k-major intermediate at A_OFF ([col][PAD] layout)
__device__ void epi_relu(float* sm, const float* __restrict__ bias,
                         int tid, float acc[2][4][4]) {
    float* B = sm + A_OFF;
    int warp = tid >> 5, lane = tid & 31;
    int lr = lane >> 2, lk = lane & 3;
    int rowb = (warp >> 2) * 32, colb = (warp & 3) * 32;
    #pragma unroll
    for (int rt = 0; rt < 2; rt++)
        #pragma unroll
        for (int ct = 0; ct < 4; ct++) {
            int row = rowb + rt * 16 + lr, col = colb + ct * 8 + 2 * lk;
            float b0 = bias[col], b1 = bias[col + 1];
            B[(col)     * PAD + row]     = to_tf32(fmaxf(acc[rt][ct][0] + b0, 0.f));
            B[(col + 1) * PAD + row]     = to_tf32(fmaxf(acc[rt][ct][1] + b1, 0.f));
            B[(col)     * PAD + row + 8] = to_tf32(fmaxf(acc[rt][ct][2] + b0, 0.f));
            B[(col + 1) * PAD + row + 8] = to_tf32(fmaxf(acc[rt][ct][3] + b1, 0.f));
        }
}

// raw epilogue (no bias) -> k-major intermediate at A_OFF
__device__ void epi_raw(float* sm, int tid, float acc[2][4][4]) {
    float* B = sm + A_OFF;
    int warp = tid >> 5, lane = tid & 31;
    int lr = lane >> 2, lk = lane & 3;
    int rowb = (warp >> 2) * 32, colb = (warp & 3) * 32;
    #pragma unroll
    for (int rt = 0; rt < 2; rt++)
        #pragma unroll
        for (int ct = 0; ct < 4; ct++) {
            int row = rowb + rt * 16 + lr, col = colb + ct * 8 + 2 * lk;
            B[(col)     * PAD + row]     = acc[rt][ct][0];
            B[(col + 1) * PAD + row]     = acc[rt][ct][1];
            B[(col)     * PAD + row + 8] = acc[rt][ct][2];
            B[(col + 1) * PAD + row + 8] = acc[rt][ct][3];
        }
}

// ---------------------------------------------------------------------------
// hs = [s,t] @ hs_W + hs_b
// ---------------------------------------------------------------------------
__global__ __launch_bounds__(TPB, 1)
void hs_kernel(const float* __restrict__ s, const float* __restrict__ t,
               const float* __restrict__ hsW, const float* __restrict__ hsb,
               float* __restrict__ out)
{
    extern __shared__ float sm[];
    int tid = threadIdx.x;
    int n0 = blockIdx.x * 128;

    {
        int r = tid & 127, part = tid >> 7;
        const float* p0 = s + (size_t)(n0 + r) * Dm;
        const float* p1 = t + (size_t)(n0 + r) * Dm;
        #pragma unroll
        for (int j = 0; j < 16; j++) {
            int q = part + 4 * j;
            float4 v = (q < 32) ? ((const float4*)p0)[q] : ((const float4*)p1)[q - 32];
            int k = q * 4;
            sm[A_OFF + (size_t)(k + 0) * PAD + r] = to_tf32(v.x);
            sm[A_OFF + (size_t)(k + 1) * PAD + r] = to_tf32(v.y);
            sm[A_OFF + (size_t)(k + 2) * PAD + r] = to_tf32(v.z);
            sm[A_OFF + (size_t)(k + 3) * PAD + r] = to_tf32(v.w);
        }
    }
    __syncthreads();

    float acc[2][4][4];
    #pragma unroll
    for (int i = 0; i < 2; i++)
        #pragma unroll
        for (int j = 0; j < 4; j++)
            #pragma unroll
            for (int q = 0; q < 4; q++) acc[i][j][q] = 0.f;

    gemm128(sm, hsW, 256, tid, acc);

    {
        int warp = tid >> 5, lane = tid & 31;
        int lr = lane >> 2, lk = lane & 3;
        int rowb = (warp >> 2) * 32, colb = (warp & 3) * 32;
        #pragma unroll
        for (int rt = 0; rt < 2; rt++)
            #pragma unroll
            for (int ct = 0; ct < 4; ct++) {
                int row = rowb + rt * 16 + lr, col = colb + ct * 8 + 2 * lk;
                float b0 = hsb[col], b1 = hsb[col + 1];
                float2 v0 = make_float2(acc[rt][ct][0] + b0, acc[rt][ct][1] + b1);
                float2 v1 = make_float2(acc[rt][ct][2] + b0, acc[rt][ct][3] + b1);
                *(float2*)(out + (size_t)(n0 + row) * Dm + col)     = v0;
                *(float2*)(out + (size_t)(n0 + row + 8) * Dm + col) = v1;
            }
    }
}

// ---------------------------------------------------------------------------
// per-level fused kernel: 64 nodes (128 gathered rows) per block
// ---------------------------------------------------------------------------
__global__ __launch_bounds__(TPB, 1)
void level_kernel(int li, const int* __restrict__ fanin,
                  const float* __restrict__ W1, const float* __restrict__ b1,
                  const float* __restrict__ W2, const float* __restrict__ b2,
                  const float* __restrict__ W3, const float* __restrict__ b3,
                  const float* __restrict__ Wi, const float* __restrict__ bi,
                  const float* __restrict__ bh,
                  const float* __restrict__ hs, float* __restrict__ hf)
{
    extern __shared__ float sm[];
    const int TILES = Mn / 64;  // 512
    int g = blockIdx.x / TILES, tile = blockIdx.x - g * TILES;
    int count = g_counts[li][g];
    int base = tile * 64;
    if (base >= count) return;
    int valid = min(64, count - base);
    int tid = threadIdx.x;

    int* s_nodes = (int*)((char*)sm + NODES_B);
    int* s_src   = (int*)((char*)sm + SRC_B);

    if (tid < 64) {
        int i = base + tid;
        s_nodes[tid] = g_lists[li][g][i < count ? i : base];
    }
    __syncthreads();
    if (tid < 128) {
        int i = tid >> 1, f = tid & 1;
        int m = s_nodes[i];
        s_src[tid] = li * Mn + fanin[((size_t)li * Mn + m) * 2 + f];
    }
    __syncthreads();

    // gather [hs||hf] of 128 source rows into A [256][PAD]
    {
        int r = tid & 127, part = tid >> 7;
        int srow = s_src[r];
        const float* p0 = hs + (size_t)srow * Dm;
        const float* p1 = hf + (size_t)srow * Dm;
        #pragma unroll
        for (int j = 0; j < 16; j++) {
            int q = part + 4 * j;
            float4 v = (q < 32) ? ((const float4*)p0)[q] : ((const float4*)p1)[q - 32];
            int k = q * 4;
            sm[A_OFF + (size_t)(k + 0) * PAD + r] = to_tf32(v.x);
            sm[A_OFF + (size_t)(k + 1) * PAD + r] = to_tf32(v.y);
            sm[A_OFF + (size_t)(k + 2) * PAD + r] = to_tf32(v.z);
            sm[A_OFF + (size_t)(k + 3) * PAD + r] = to_tf32(v.w);
        }
    }
    __syncthreads();

    float acc[2][4][4];
    #define ZACC() { _Pragma("unroll") for (int i = 0; i < 2; i++) \
                     _Pragma("unroll") for (int j = 0; j < 4; j++) \
                     _Pragma("unroll") for (int q = 0; q < 4; q++) acc[i][j][q] = 0.f; }

    // GEMM1: h1 = relu(X @ W1 + b1), K=256
    ZACC();
    gemm128(sm, W1 + (size_t)g * 256 * 128, 256, tid, acc);
    epi_relu(sm, b1 + g * Dm, tid, acc);
    __syncthreads();

    // GEMM2: h2 = relu(h1 @ W2 + b2), K=128
    ZACC();
    gemm128(sm, W2 + (size_t)g * 128 * 128, 128, tid, acc);
    epi_relu(sm, b2 + g * Dm, tid, acc);
    __syncthreads();

    // GEMM3: m = h2 @ W3 (raw), K=128
    ZACC();
    gemm128(sm, W3 + (size_t)g * 128 * 128, 128, tid, acc);
    epi_raw(sm, tid, acc);
    __syncthreads();

    // pair-sum fanin rows + 2*b3 -> msg [128 col][72] (tf32)
    {
        const float* mbuf = sm + A_OFF;
        float* msg = sm + MSG_OFF;
        #pragma unroll
        for (int j = 0; j < 16; j++) {
            int idx = tid + j * 512;            // 8192 = 128 cols x 64 nodes
            int col = idx >> 6, node = idx & 63;
            float v = mbuf[col * PAD + 2 * node] + mbuf[col * PAD + 2 * node + 1]
                    + 2.f * b3[g * Dm + col];
            msg[col * 72 + node] = to_tf32(v);
        }
    }
    __syncthreads();

    // GEMM4: gi = msg @ Wi (M=64, N=384, K=128), double-buffered W staging,
    // warp partition: nodes (warp&3)*16, cols (warp>>2)*32 in EACH gate section
    // {0,128,256}. Each thread then holds r/z/n for its own (node,d) pairs
    // -> in-register GRU, direct global writes. No gibuf, no extra barriers.
    {
        const float* msg = sm + MSG_OFF;
        float* Wsh = sm + W_OFF;                // 2 x 6272 floats ([16][392])
        int warp = tid >> 5, lane = tid & 31;
        int lr = lane >> 2, lk = lane & 3;
        int rowb = (warp & 3) * 16, cb32 = (warp >> 2) * 32;
        const float* Wg = Wi + (size_t)g * 128 * 384;

        int kk[3], qq[3];
        #pragma unroll
        for (int j = 0; j < 3; j++) {
            int idx = tid + j * 512;            // 1536 float4 = 16 x 96
            kk[j] = idx / 96; qq[j] = idx - kk[j] * 96;
        }

        float acc4[3][4][4];                    // [gate section][tile][frag]
        #pragma unroll
        for (int i = 0; i < 3; i++)
            #pragma unroll
            for (int j = 0; j < 4; j++)
                #pragma unroll
                for (int q = 0; q < 4; q++) acc4[i][j][q] = 0.f;

        // prologue: stage chunk 0 into buf0, prefetch chunk 1
        float4 pre[3];
        #pragma unroll
        for (int j = 0; j < 3; j++) {
            pre[j] = ((const float4*)(Wg + (size_t)kk[j] * 384))[qq[j]];
            *(float4*)(Wsh + kk[j] * 392 + qq[j] * 4) = tf32x4(pre[j]);
        }
        #pragma unroll
        for (int j = 0; j < 3; j++)
            pre[j] = ((const float4*)(Wg + (size_t)(16 + kk[j]) * 384))[qq[j]];
        __syncthreads();

        for (int c = 0; c < 8; c++) {           // 8 chunks of 16 K
            const float* Wb = Wsh + (c & 1) * 6272;
            int kc = c * 16;
            #pragma unroll
            for (int s2 = 0; s2 < 2; s2++) {
                int k0 = s2 * 8;
                float a[4];
                int row = rowb + lr;
                a[0] = msg[(size_t)(kc + k0 + lk) * 72 + row];
                a[1] = msg[(size_t)(kc + k0 + lk) * 72 + row + 8];
                a[2] = msg[(size_t)(kc + k0 + 4 + lk) * 72 + row];
                a[3] = msg[(size_t)(kc + k0 + 4 + lk) * 72 + row + 8];
                #pragma unroll
                for (int sec = 0; sec < 3; sec++)
                    #pragma unroll
                    for (int t = 0; t < 4; t++) {
                        int col = sec * 128 + cb32 + t * 8 + lr;
                        float b[2];
                        b[0] = Wb[(k0 + lk) * 392 + col];
                        b[1] = Wb[(k0 + 4 + lk) * 392 + col];
                        mma8(acc4[sec][t], a, b);
                    }
            }
            if (c + 1 < 8) {
                float* Wn = Wsh + ((c + 1) & 1) * 6272;
                #pragma unroll
                for (int j = 0; j < 3; j++)
                    *(float4*)(Wn + kk[j] * 392 + qq[j] * 4) = tf32x4(pre[j]);
                if (c + 2 < 8) {
                    #pragma unroll
                    for (int j = 0; j < 3; j++)
                        pre[j] = ((const float4*)(Wg + (size_t)((c + 2) * 16 + kk[j]) * 384))[qq[j]];
                }
            }
            __syncthreads();
        }

        // in-register GRU (h == 0 -> gh == bh) + direct hf writes
        int node0 = rowb + lr, node1 = node0 + 8;
        int m0 = s_nodes[node0], m1 = s_nodes[node1];
        bool v0 = node0 < valid, v1 = node1 < valid;
        float* dst0 = hf + ((size_t)(li + 1) * Mn + m0) * Dm;
        float* dst1 = hf + ((size_t)(li + 1) * Mn + m1) * Dm;
        const float* big = bi + g * 384;
        const float* bhg = bh + g * 384;
        #pragma unroll
        for (int t = 0; t < 4; t++) {
            int d = cb32 + t * 8 + 2 * lk;
            float o[4];
            #pragma unroll
            for (int e = 0; e < 2; e++) {       // e = d offset (0/1)
                int dd = d + e;
                float br = big[dd]       + bhg[dd];
                float bz = big[128 + dd] + bhg[128 + dd];
                float bn = big[256 + dd];
                float hn = bhg[256 + dd];
                #pragma unroll
                for (int r2 = 0; r2 < 2; r2++) { // r2 = node row (0 -> node0, 1 -> node1)
                    int q = r2 * 2 + e;
                    float gr = acc4[0][t][q] + br;
                    float gz = acc4[1][t][q] + bz;
                    float rg = 1.f / (1.f + expf(-gr));
                    float zg = 1.f / (1.f + expf(-gz));
                    float ng = tanhf(acc4[2][t][q] + bn + rg * hn);
                    o[q] = (1.f - zg) * ng;
                }
            }
            if (v0) *(float2*)(dst0 + d) = make_float2(o[0], o[1]);
            if (v1) *(float2*)(dst1 + d) = make_float2(o[2], o[3]);
        }
    }
}

// ---------------------------------------------------------------------------
extern "C" void kernel_launch(void* const* d_in, const int* in_sizes, int n_in,
                              void* d_out, int out_size)
{
    const float* s    = (const float*)d_in[0];
    const float* t    = (const float*)d_in[1];
    const int*   gate = (const int*)  d_in[2];
    const int*   fan  = (const int*)  d_in[3];
    const float* hsW  = (const float*)d_in[4];
    const float* hsb  = (const float*)d_in[5];
    const float* W1   = (const float*)d_in[6];
    const float* b1   = (const float*)d_in[7];
    const float* W2   = (const float*)d_in[8];
    const float* b2   = (const float*)d_in[9];
    const float* W3   = (const float*)d_in[10];
    const float* b3   = (const float*)d_in[11];
    const float* Wi   = (const float*)d_in[12];
    // d_in[13] = gru_Wh: provably unused (h == 0 at every level)
    const float* bi   = (const float*)d_in[14];
    const float* bh   = (const float*)d_in[15];

    float* hs = (float*)d_out;
    float* hf = hs + (size_t)Nn * Dm;

    cudaFuncSetAttribute(hs_kernel,    cudaFuncAttributeMaxDynamicSharedMemorySize, SMEM_TOTAL);
    cudaFuncSetAttribute(level_kernel, cudaFuncAttributeMaxDynamicSharedMemorySize, SMEM_TOTAL);

    zero_kernel<<<(Mn * Dm / 4) / TPB, TPB>>>(hf);
    bucket_kernel<<<(LVLS * Mn + TPB - 1) / TPB, TPB>>>(gate);
    hs_kernel<<<Nn / 128, TPB, SMEM_TOTAL>>>(s, t, hsW, hsb, hs);
    for (int li = 0; li < LVLS; li++) {
        level_kernel<<<Gg * (Mn / 64), TPB, SMEM_TOTAL>>>(
            li, fan, W1, b1, W2, b2, W3, b3, Wi, bi, bh, hs, hf);
    }
}